// round 6
// baseline (speedup 1.0000x reference)
#include <cuda_runtime.h>
#include <cstdint>

#define CIN 256
#define COUT 256
#define NB 32
#define ZSZ (NB * COUT * 36)
#define XSZ (NB * COUT * 900)
#define OSZ (NB * COUT * 625)
#define WQ_PER_PATH (9 * 256 * 512)

__device__ int8_t g_wq[4][WQ_PER_PATH];   // [path][(tap*256+oc)*512 + (B1:0..255 | B2:256..511)]
__device__ float g_bias[4][COUT];
__device__ unsigned g_maxbits[6];         // |x|, |z|, |b| per path (float bits)
__device__ float g_zf[2][ZSZ];
__device__ float g_xf[2][XSZ];

struct PrepArgs {
    const float* w[4];
    const float* g[4];
    const float* b[4];
    const float* m[4];
    const float* v[4];
};

// ============================ helpers ========================================
__device__ __forceinline__ uint32_t smem_u32(const void* p) {
    uint32_t a;
    asm("{ .reg .u64 t; cvta.to.shared.u64 t, %1; cvt.u32.u64 %0, t; }"
        : "=r"(a) : "l"(p));
    return a;
}
__device__ __forceinline__ void cp16(uint32_t dst, const void* src) {
    asm volatile("cp.async.cg.shared.global [%0], [%1], 16;" :: "r"(dst), "l"(src));
}
__device__ __forceinline__ void cp_commit() {
    asm volatile("cp.async.commit_group;" ::: "memory");
}
template <int N>
__device__ __forceinline__ void cp_wait() {
    asm volatile("cp.async.wait_group %0;" :: "n"(N) : "memory");
}

#define LDSM4(r, addr)                                                         \
    asm volatile("ldmatrix.sync.aligned.m8n8.x4.shared.b16 {%0,%1,%2,%3},[%4];"\
        : "=r"((r)[0]), "=r"((r)[1]), "=r"((r)[2]), "=r"((r)[3]) : "r"(addr))

#define IMMA(d, a, b0, b1)                                                     \
    asm volatile("mma.sync.aligned.m16n8k32.row.col.s32.s8.s8.s32 "            \
        "{%0,%1,%2,%3}, {%4,%5,%6,%7}, {%8,%9}, {%0,%1,%2,%3};"                \
        : "+r"((d)[0]), "+r"((d)[1]), "+r"((d)[2]), "+r"((d)[3])               \
        : "r"((a)[0]), "r"((a)[1]), "r"((a)[2]), "r"((a)[3]),                  \
          "r"(b0), "r"(b1))

__device__ __forceinline__ void quant2(float v, float inv_s, int& q1, int& q2) {
    float t = v * inv_s;
    q1 = __float2int_rn(t);
    int a2 = __float2int_rn((t - (float)q1) * 256.f);
    q2 = max(-127, min(127, a2));
}
__device__ __forceinline__ uint32_t pack4(int a, int b, int c, int d) {
    return (uint32_t)(a & 255) | ((uint32_t)(b & 255) << 8) |
           ((uint32_t)(c & 255) << 16) | ((uint32_t)(d & 255) << 24);
}

// ============================ scale pass =====================================
__global__ void init_kernel() {
    if (threadIdx.x < 6) g_maxbits[threadIdx.x] = 0u;
}

__global__ void scale_kernel(const float* __restrict__ x,
                             const float* __restrict__ z, PrepArgs a) {
    float mx[6] = {0.f, 0.f, 0.f, 0.f, 0.f, 0.f};
    int tid = blockIdx.x * blockDim.x + threadIdx.x;
    int stride = gridDim.x * blockDim.x;
    for (int i = tid; i < NB * CIN * 1024; i += stride)
        mx[0] = fmaxf(mx[0], fabsf(x[i]));
    for (int i = tid; i < NB * CIN * 64; i += stride)
        mx[1] = fmaxf(mx[1], fabsf(z[i]));
#pragma unroll
    for (int p = 0; p < 4; p++)
        for (int i = tid; i < COUT * CIN * 9; i += stride) {
            int oc = i / (CIN * 9);
            float inv = a.g[p][oc] * rsqrtf(a.v[p][oc] + 1e-5f);
            mx[2 + p] = fmaxf(mx[2 + p], fabsf(a.w[p][i] * inv));
        }
#pragma unroll
    for (int k = 0; k < 6; k++) {
        float v = mx[k];
#pragma unroll
        for (int o = 16; o > 0; o >>= 1)
            v = fmaxf(v, __shfl_xor_sync(0xffffffffu, v, o));
        if ((threadIdx.x & 31) == 0)
            atomicMax(&g_maxbits[k], __float_as_uint(v));
    }
}

// ============================ prep ===========================================
__global__ void prep_kernel(PrepArgs a) {
    const int TOTAL = 4 * 9 * 256 * 256;
    for (int i = blockIdx.x * blockDim.x + threadIdx.x; i < TOTAL;
         i += gridDim.x * blockDim.x) {
        int path = i / (9 * 256 * 256);
        int q    = i % (9 * 256 * 256);
        int tap  = q >> 16;
        int oc   = (q >> 8) & 255;
        int cin  = q & 255;
        float inv = a.g[path][oc] * rsqrtf(a.v[path][oc] + 1e-5f);
        float ws  = a.w[path][oc * 2304 + cin * 9 + tap] * inv;
        float inv_sb = 126.f / __uint_as_float(g_maxbits[2 + path]);
        int b1, b2;
        quant2(ws, inv_sb, b1, b2);
        g_wq[path][(tap * 256 + oc) * 512 + cin]       = (int8_t)b1;
        g_wq[path][(tap * 256 + oc) * 512 + 256 + cin] = (int8_t)b2;
        if (i < 4 * 256) {
            int p2 = i >> 8, oc2 = i & 255;
            float inv2 = a.g[p2][oc2] * rsqrtf(a.v[p2][oc2] + 1e-5f);
            g_bias[p2][oc2] = a.b[p2][oc2] - a.m[p2][oc2] * inv2;
        }
    }
}

// ============================ conv (int8 IMMA implicit GEMM) =================
// Block: M=64 px x N=64 oc, 128 thr, 4 warps (2x2), warp tile 32x32.
// K = 256 cin x 9 taps (chunks of 32). Terms: S11, Scross=A1B2+A2B1, S22.
// blocks 0..3839 : x-mode (2 out rows x 32 cols, never crosses image)
// blocks 3840..3983: z-mode (64 dense px; 1152 = 18*64)
#define BSTRIDE 80u
#define BBUF    (64u * BSTRIDE)        // 5120
#define RAW_OFF (2u * BBUF)            // 10240
#define SSTRIDE 48u
#define NSLOTS  192u
#define SLABB   (NSLOTS * SSTRIDE)     // 9216
#define CONV_SMEM (RAW_OFF + 2u * SLABB)   // 28672

__device__ __forceinline__ void copy_B(uint32_t sBu, const int8_t* wq,
                                       int ocb, int g, int tid) {
    int chunk = 0, t = g;
    while (t >= 9) { t -= 9; chunk++; }
    const int buf = g & 1, c0 = chunk * 32;
    const int8_t* base = wq + (size_t)(t * 256 + ocb) * 512;
#pragma unroll
    for (int k = 0; k < 2; k++) {
        int id = tid + k * 128;            // 256 cp16
        int n = id >> 2, part = id & 3;
        uint32_t dst = sBu + buf * BBUF + n * BSTRIDE + part * 16;
        cp16(dst, base + (size_t)n * 512 + (part >> 1) * 256 + c0 + (part & 1) * 16);
    }
    cp_commit();
}

__global__ __launch_bounds__(128, 3)
void conv_mma_kernel(const float* __restrict__ zin,
                     const float* __restrict__ xin) {
    extern __shared__ __align__(16) char smem[];
    const int tid = threadIdx.x, lid = tid & 31, wid = tid >> 5;
    const int warp_m = wid >> 1, warp_n = wid & 1;
    const uint32_t sBu  = smem_u32(smem);
    const uint32_t rawu = sBu + RAW_OFF;

    const int bid = blockIdx.x;
    const bool zmode = (bid >= 3840);
    int branch, ocb;
    int img0 = 0, y0 = 0;               // x-mode
    int P0 = 0, img_base = 0;           // z-mode
    if (zmode) {
        int zb = bid - 3840;            // 0..143
        int bo = zb / 18;
        branch = bo >> 2; ocb = (bo & 3) * 64;
        P0 = (zb - bo * 18) * 64;
        img_base = P0 / 36;
    } else {
        int bo = bid / 480;
        branch = bo >> 2; ocb = (bo & 3) * 64;
        int R0 = (bid - bo * 480) * 2;  // even -> rows never cross image
        img0 = R0 / 30; y0 = R0 - img0 * 30;
    }
    const int path = zmode ? 2 * branch : 1 + 2 * branch;
    const int8_t* wq = g_wq[path];
    const float* in = zmode ? zin : xin;
    const float inv_sa = 126.f / __uint_as_float(g_maxbits[zmode ? 1 : 0]);

    int S11[2][4][4], Sx[2][4][4], S22[2][4][4];
#pragma unroll
    for (int t = 0; t < 2; t++)
#pragma unroll
        for (int j = 0; j < 4; j++)
#pragma unroll
            for (int e = 0; e < 4; e++) {
                S11[t][j][e] = 0; Sx[t][j][e] = 0; S22[t][j][e] = 0;
            }

    copy_B(sBu, wq, ocb, 0, tid);

    int chunk = 0, tap = 0;
#pragma unroll 1
    for (int g = 0; g < 72; g++) {
        const int buf = g & 1;
        __syncthreads();
        if (tap == 0) {
            const int c0 = chunk * 32;
            if (zmode) {
#pragma unroll 4
                for (int k = 0; k < 12; k++) {
                    int id = tid + k * 128;          // 1536
                    int slot = id % 192, q = id / 192;
                    int ir = slot >> 6, pos = slot & 63;
                    int img = img_base + ir;
                    float v0 = 0.f, v1 = 0.f, v2 = 0.f, v3 = 0.f;
                    if (img < 32) {
                        const float* src = in + (((size_t)img * 256 + c0 + q * 4) << 6) + pos;
                        v0 = src[0]; v1 = src[64]; v2 = src[128]; v3 = src[192];
                    }
                    int a1[4], a2[4];
                    quant2(v0, inv_sa, a1[0], a2[0]);
                    quant2(v1, inv_sa, a1[1], a2[1]);
                    quant2(v2, inv_sa, a1[2], a2[2]);
                    quant2(v3, inv_sa, a1[3], a2[3]);
                    uint32_t off = RAW_OFF + slot * SSTRIDE + q * 4;
                    *(uint32_t*)(smem + off)         = pack4(a1[0], a1[1], a1[2], a1[3]);
                    *(uint32_t*)(smem + off + SLABB) = pack4(a2[0], a2[1], a2[2], a2[3]);
                }
            } else {
#pragma unroll 4
                for (int k = 0; k < 8; k++) {
                    int id = tid + k * 128;          // 1024
                    int slot = id & 127, q = id >> 7;
                    int r = slot >> 5, col = slot & 31;
                    const float* src = in +
                        ((((size_t)img0 * 256 + c0 + q * 4) * 32) + y0 + r) * 32 + col;
                    int a1[4], a2[4];
                    quant2(src[0],    inv_sa, a1[0], a2[0]);
                    quant2(src[1024], inv_sa, a1[1], a2[1]);
                    quant2(src[2048], inv_sa, a1[2], a2[2]);
                    quant2(src[3072], inv_sa, a1[3], a2[3]);
                    uint32_t off = RAW_OFF + slot * SSTRIDE + q * 4;
                    *(uint32_t*)(smem + off)         = pack4(a1[0], a1[1], a1[2], a1[3]);
                    *(uint32_t*)(smem + off + SLABB) = pack4(a2[0], a2[1], a2[2], a2[3]);
                }
            }
        }
        if (g + 1 < 72) { copy_B(sBu, wq, ocb, g + 1, tid); cp_wait<1>(); }
        else            { cp_wait<0>(); }
        __syncthreads();

        const int dy = tap / 3, dx = tap - dy * 3;
        uint32_t aaddr[2];
#pragma unroll
        for (int t = 0; t < 2; t++) {
            int m = warp_m * 32 + t * 16 + (lid & 7) + ((lid >> 3) & 1) * 8;
            int slot;
            if (zmode) {
                int p = P0 + m;
                int pim = p / 36;
                int q = p - pim * 36;
                int qy = q / 6;
                slot = (pim - img_base) * 64 + (qy + dy) * 8 + (q - qy * 6) + dx;
            } else {
                int i = m >> 5, x = m & 31;
                slot = (i + dy) * 32 + x + dx;
            }
            aaddr[t] = rawu + slot * SSTRIDE + ((lid >> 4) << 4);
        }
        const int bcol = warp_n * 32 + (lid & 7) + (lid >> 4) * 8;
        const uint32_t bbase = sBu + buf * BBUF + bcol * BSTRIDE + (((lid >> 3) & 1) << 4);

        uint32_t A1[2][4], A2[2][4], B1[2][4], B2[2][4];
#pragma unroll
        for (int t = 0; t < 2; t++) LDSM4(A1[t], aaddr[t]);
#pragma unroll
        for (int t = 0; t < 2; t++) LDSM4(A2[t], aaddr[t] + SLABB);
#pragma unroll
        for (int h = 0; h < 2; h++) LDSM4(B1[h], bbase + h * (16 * BSTRIDE));
#pragma unroll
        for (int h = 0; h < 2; h++) LDSM4(B2[h], bbase + h * (16 * BSTRIDE) + 32);

#pragma unroll
        for (int t = 0; t < 2; t++)
#pragma unroll
            for (int j = 0; j < 4; j++) {
                uint32_t b1a = B1[j >> 1][(j & 1) * 2], b1b = B1[j >> 1][(j & 1) * 2 + 1];
                uint32_t b2a = B2[j >> 1][(j & 1) * 2], b2b = B2[j >> 1][(j & 1) * 2 + 1];
                IMMA(S11[t][j], A1[t], b1a, b1b);
                IMMA(Sx[t][j],  A1[t], b2a, b2b);
                IMMA(Sx[t][j],  A2[t], b1a, b1b);
                IMMA(S22[t][j], A2[t], b2a, b2b);
            }

        if (++tap == 9) { tap = 0; chunk++; }
    }
    __syncthreads();

    // ---- epilogue: combine terms, transpose via smem, coalesced out --------
    const float osc = (__uint_as_float(g_maxbits[zmode ? 1 : 0]) / 126.f) *
                      (__uint_as_float(g_maxbits[2 + path]) / 126.f);
    float* sEp = (float*)smem;                       // [64 oc][68]
    float* sBias = (float*)(smem + 64 * 68 * 4);
    if (tid < 64) sBias[tid] = g_bias[path][ocb + tid];
#pragma unroll
    for (int t = 0; t < 2; t++) {
        int r0 = warp_m * 32 + t * 16 + (lid >> 2);
#pragma unroll
        for (int j = 0; j < 4; j++) {
            int c = warp_n * 32 + j * 8 + 2 * (lid & 3);
#pragma unroll
            for (int e = 0; e < 4; e++) {
                float f = (float)S11[t][j][e] + (float)Sx[t][j][e] * 0x1p-8f +
                          (float)S22[t][j][e] * 0x1p-16f;
                int cc = c + (e & 1);
                int rr = r0 + (e >> 1) * 8;
                sEp[cc * 68 + rr] = f;
            }
        }
    }
    __syncthreads();

    const int m = tid & 63, h = tid >> 6;
    if (zmode) {
        int p = P0 + m;
        int img = p / 36;
        int q = p - img * 36;
        float* op = g_zf[branch] + ((size_t)img * COUT + ocb + h * 32) * 36 + q;
#pragma unroll 8
        for (int k = 0; k < 32; k++)
            op[(size_t)k * 36] = sEp[(h * 32 + k) * 68 + m] * osc + sBias[h * 32 + k];
    } else {
        int i = m >> 5, x = m & 31;
        if (x < 30) {
            int y = y0 + i;
            float* op = g_xf[branch] + ((size_t)img0 * COUT + ocb + h * 32) * 900 + y * 30 + x;
#pragma unroll 8
            for (int k = 0; k < 32; k++)
                op[(size_t)k * 900] = sEp[(h * 32 + k) * 68 + m] * osc + sBias[h * 32 + k];
        }
    }
}

// ============================ depthwise xcorr ================================
__global__ __launch_bounds__(640)
void xcorr_kernel(float* __restrict__ out) {
    __shared__ float s_x[900];
    __shared__ float s_z[36];
    const int branch = blockIdx.y;
    const int bc = blockIdx.x;
    const int tid = threadIdx.x;
    if (tid < 36) s_z[tid] = g_zf[branch][(size_t)bc * 36 + tid];
    for (int i = tid; i < 900; i += 640) s_x[i] = g_xf[branch][(size_t)bc * 900 + i];
    __syncthreads();
    if (tid < 625) {
        int oy = tid / 25, ox = tid % 25;
        float s = 0.f;
#pragma unroll
        for (int u = 0; u < 6; u++)
#pragma unroll
            for (int v = 0; v < 6; v++)
                s = fmaf(s_z[u * 6 + v], s_x[(oy + u) * 30 + ox + v], s);
        out[(size_t)branch * OSZ + (size_t)bc * 625 + tid] = s;
    }
}

// ============================ launch =========================================
extern "C" void kernel_launch(void* const* d_in, const int* in_sizes, int n_in,
                              void* d_out, int out_size) {
    const float* z = (const float*)d_in[0];
    const float* x = (const float*)d_in[1];

    PrepArgs pa;
    for (int p = 0; p < 4; p++) {
        pa.w[p] = (const float*)d_in[2 + p * 5 + 0];
        pa.g[p] = (const float*)d_in[2 + p * 5 + 1];
        pa.b[p] = (const float*)d_in[2 + p * 5 + 2];
        pa.m[p] = (const float*)d_in[2 + p * 5 + 3];
        pa.v[p] = (const float*)d_in[2 + p * 5 + 4];
    }

    cudaFuncSetAttribute(conv_mma_kernel,
                         cudaFuncAttributeMaxDynamicSharedMemorySize, CONV_SMEM);
    cudaFuncSetAttribute(conv_mma_kernel,
                         cudaFuncAttributePreferredSharedMemoryCarveout, 100);

    init_kernel<<<1, 32>>>();
    scale_kernel<<<256, 256>>>(x, z, pa);
    prep_kernel<<<1152, 256>>>(pa);
    conv_mma_kernel<<<3984, 128, CONV_SMEM>>>(z, x);
    xcorr_kernel<<<dim3(NB * COUT, 2), 640>>>((float*)d_out);
}

// round 7
// speedup vs baseline: 3.6976x; 3.6976x over previous
#include <cuda_runtime.h>
#include <cuda_bf16.h>
#include <cstdint>

#define CIN 256
#define COUT 256
#define NB 32
#define ZSZ (NB * COUT * 36)
#define XSZ (NB * COUT * 900)
#define OSZ (NB * COUT * 625)

// Winograd sizes: x: 15x15 tiles/img * 32 = 7200 (pad 7296 = 57*128)
//                 z: 3x3 tiles/img * 32 = 288 (pad 384 = 3*128)
#define NTX 7296
#define NTZ 384
#define VSX ((size_t)NTX * 512)
#define VSZ ((size_t)NTZ * 512)

__device__ __align__(16) __nv_bfloat16 g_wU[4][16 * 256 * 512]; // [path][(pos*256+oc)*512 + comp*256+cin]
__device__ float g_bias[4][COUT];
__device__ __align__(16) __nv_bfloat16 g_V[16 * NTX * 512];     // [pos][tile][comp*256+cin]
__device__ __align__(16) __nv_bfloat16 g_Vz[16 * NTZ * 512];
__device__ float g_M[2][16 * NTX * 256];                        // [branch][pos][tile][oc]
__device__ float g_Mz[2][16 * NTZ * 256];
__device__ float g_zf[2][ZSZ];
__device__ float g_xf[2][XSZ];

struct PrepArgs {
    const float* w[4];
    const float* g[4];
    const float* b[4];
    const float* m[4];
    const float* v[4];
};

// ============================ helpers ========================================
__device__ __forceinline__ uint32_t smem_u32(const void* p) {
    uint32_t a;
    asm("{ .reg .u64 t; cvta.to.shared.u64 t, %1; cvt.u32.u64 %0, t; }"
        : "=r"(a) : "l"(p));
    return a;
}
__device__ __forceinline__ void cp16(uint32_t dst, const void* src) {
    asm volatile("cp.async.cg.shared.global [%0], [%1], 16;" :: "r"(dst), "l"(src));
}
__device__ __forceinline__ void cp_commit() {
    asm volatile("cp.async.commit_group;" ::: "memory");
}
template <int N>
__device__ __forceinline__ void cp_wait() {
    asm volatile("cp.async.wait_group %0;" :: "n"(N) : "memory");
}

#define LDSM4(r, addr)                                                         \
    asm volatile("ldmatrix.sync.aligned.m8n8.x4.shared.b16 {%0,%1,%2,%3},[%4];"\
        : "=r"((r)[0]), "=r"((r)[1]), "=r"((r)[2]), "=r"((r)[3]) : "r"(addr))

#define MMA(d, a, b0, b1)                                                      \
    asm volatile("mma.sync.aligned.m16n8k16.row.col.f32.bf16.bf16.f32 "        \
        "{%0,%1,%2,%3}, {%4,%5,%6,%7}, {%8,%9}, {%0,%1,%2,%3};"                \
        : "+f"((d)[0]), "+f"((d)[1]), "+f"((d)[2]), "+f"((d)[3])               \
        : "r"((a)[0]), "r"((a)[1]), "r"((a)[2]), "r"((a)[3]),                  \
          "r"(b0), "r"(b1))

__device__ __forceinline__ void bsplit(float v, __nv_bfloat16& hi, __nv_bfloat16& lo) {
    hi = __float2bfloat16(v);
    lo = __float2bfloat16(v - __bfloat162float(hi));
}

// ============================ prep: weight transform =========================
// U = G g G^T (4x4) per (path, oc, cin); BN folded; bf16 hi/lo split.
__global__ void prep_kernel(PrepArgs a) {
    int i = blockIdx.x * blockDim.x + threadIdx.x;       // 262144 items
    int path = i >> 16;
    int oc   = (i >> 8) & 255;
    int cin  = i & 255;
    float inv = a.g[path][oc] * rsqrtf(a.v[path][oc] + 1e-5f);
    const float* wp = a.w[path] + oc * 2304 + cin * 9;
    float w[3][3];
#pragma unroll
    for (int r = 0; r < 3; r++)
#pragma unroll
        for (int c = 0; c < 3; c++) w[r][c] = wp[r * 3 + c] * inv;

    float T[4][3];
#pragma unroll
    for (int j = 0; j < 3; j++) {
        T[0][j] = w[0][j];
        T[1][j] = 0.5f * (w[0][j] + w[1][j] + w[2][j]);
        T[2][j] = 0.5f * (w[0][j] - w[1][j] + w[2][j]);
        T[3][j] = w[2][j];
    }
#pragma unroll
    for (int r = 0; r < 4; r++) {
        float U[4];
        U[0] = T[r][0];
        U[1] = 0.5f * (T[r][0] + T[r][1] + T[r][2]);
        U[2] = 0.5f * (T[r][0] - T[r][1] + T[r][2]);
        U[3] = T[r][2];
#pragma unroll
        for (int c = 0; c < 4; c++) {
            __nv_bfloat16 hi, lo;
            bsplit(U[c], hi, lo);
            size_t base = ((size_t)((r * 4 + c) * 256 + oc)) * 512 + cin;
            g_wU[path][base]       = hi;
            g_wU[path][base + 256] = lo;
        }
    }
    if (i < 1024) {
        int p2 = i >> 8, oc2 = i & 255;
        float inv2 = a.g[p2][oc2] * rsqrtf(a.v[p2][oc2] + 1e-5f);
        g_bias[p2][oc2] = a.b[p2][oc2] - a.m[p2][oc2] * inv2;
    }
}

// ============================ input transforms ===============================
// V = B^T d B per tile (4x4 patch, stride 2). bf16 hi/lo.
__device__ __forceinline__ void wino_fwd(const float d[4][4], float V[4][4]) {
    float t[4][4];
#pragma unroll
    for (int j = 0; j < 4; j++) {
        t[0][j] = d[0][j] - d[2][j];
        t[1][j] = d[1][j] + d[2][j];
        t[2][j] = d[2][j] - d[1][j];
        t[3][j] = d[1][j] - d[3][j];
    }
#pragma unroll
    for (int i = 0; i < 4; i++) {
        V[i][0] = t[i][0] - t[i][2];
        V[i][1] = t[i][1] + t[i][2];
        V[i][2] = t[i][2] - t[i][1];
        V[i][3] = t[i][1] - t[i][3];
    }
}

__global__ __launch_bounds__(256)
void xform_x(const float* __restrict__ x) {
    __shared__ float sd[8][1024];
    __shared__ __align__(16) __nv_bfloat16 sV[16][16][2][8];
    const int img = blockIdx.x, cg = blockIdx.y, tid = threadIdx.x;
    const float* src = x + ((size_t)img * 256 + cg * 8) * 1024;
#pragma unroll
    for (int k = 0; k < 32; k++) {
        int lin = k * 256 + tid;
        sd[lin >> 10][lin & 1023] = src[lin];
    }
    __syncthreads();

    for (int cc = 0; cc < 15; cc++) {
        const int tl = tid >> 3, c = tid & 7;
        const int tile = cc * 16 + tl;
        if (tid < 128 && tile < 225) {
            int ty = tile / 15, tx = tile - ty * 15;
            float d[4][4], V[4][4];
#pragma unroll
            for (int i = 0; i < 4; i++)
#pragma unroll
                for (int j = 0; j < 4; j++)
                    d[i][j] = sd[c][(2 * ty + i) * 32 + 2 * tx + j];
            wino_fwd(d, V);
#pragma unroll
            for (int i = 0; i < 4; i++)
#pragma unroll
                for (int j = 0; j < 4; j++) {
                    __nv_bfloat16 hi, lo;
                    bsplit(V[i][j], hi, lo);
                    sV[tl][i * 4 + j][0][c] = hi;
                    sV[tl][i * 4 + j][1][c] = lo;
                }
        }
        __syncthreads();
#pragma unroll
        for (int k = 0; k < 2; k++) {
            int cid = k * 256 + tid;                 // 512 chunks
            int tl2 = cid >> 5, pos = (cid >> 1) & 15, comp = cid & 1;
            int tile2 = cc * 16 + tl2;
            if (tile2 < 225) {
                uint4 val = *(const uint4*)&sV[tl2][pos][comp][0];
                *(uint4*)(g_V + (size_t)pos * VSX +
                          ((size_t)img * 225 + tile2) * 512 + comp * 256 + cg * 8) = val;
            }
        }
        __syncthreads();
    }
}

__global__ __launch_bounds__(128)
void xform_z(const float* __restrict__ z) {
    __shared__ float sd[8][64];
    __shared__ __align__(16) __nv_bfloat16 sVz[9][16][2][8];
    const int img = blockIdx.x, cg = blockIdx.y, tid = threadIdx.x;
    const float* src = z + ((size_t)img * 256 + cg * 8) * 64;
#pragma unroll
    for (int k = 0; k < 4; k++) {
        int lin = k * 128 + tid;
        sd[lin >> 6][lin & 63] = src[lin];
    }
    __syncthreads();
    if (tid < 72) {
        int tl = tid >> 3, c = tid & 7;
        int ty = tl / 3, tx = tl - ty * 3;
        float d[4][4], V[4][4];
#pragma unroll
        for (int i = 0; i < 4; i++)
#pragma unroll
            for (int j = 0; j < 4; j++)
                d[i][j] = sd[c][(2 * ty + i) * 8 + 2 * tx + j];
        wino_fwd(d, V);
#pragma unroll
        for (int i = 0; i < 4; i++)
#pragma unroll
            for (int j = 0; j < 4; j++) {
                __nv_bfloat16 hi, lo;
                bsplit(V[i][j], hi, lo);
                sVz[tl][i * 4 + j][0][c] = hi;
                sVz[tl][i * 4 + j][1][c] = lo;
            }
    }
    __syncthreads();
#pragma unroll
    for (int k = 0; k < 3; k++) {
        int cid = k * 128 + tid;                     // 288 chunks
        if (cid < 288) {
            int tl = cid >> 5, pos = (cid >> 1) & 15, comp = cid & 1;
            uint4 val = *(const uint4*)&sVz[tl][pos][comp][0];
            *(uint4*)(g_Vz + (size_t)pos * VSZ +
                      ((size_t)img * 9 + tl) * 512 + comp * 256 + cg * 8) = val;
        }
    }
}

// ============================ batched GEMM ===================================
// Per block: D[128 tile, 128 oc] = V[128,256] * U[128,256]^T (3-term bf16 split)
// blocks 0..3647: x (b,o,p,mt=57); 3648..3839: z (b,o,p,mt=3)
#define ASTRIDE 144u                 // row: 32 hi (64B) | 32 lo (64B) | 16 pad
#define ABUF    (128u * ASTRIDE)     // 18432
#define BOFF    (2u * ABUF)
#define GEMM_SMEM (4u * ABUF)        // 73728

__global__ __launch_bounds__(128, 2)
void wino_gemm() {
    extern __shared__ __align__(16) char smem[];
    const int tid = threadIdx.x, lid = tid & 31, wid = tid >> 5;
    const int warp_m = wid >> 1, warp_n = wid & 1;
    const uint32_t sBu = smem_u32(smem);

    const int bid = blockIdx.x;
    const __nv_bfloat16 *vsrc, *wsrc;
    float* mdst;
    if (bid < 3648) {
        int q = bid / 57, mt = bid - q * 57;
        int p = q & 15; q >>= 4;
        int o = q & 1, b = q >> 1;
        vsrc = g_V + (size_t)p * VSX + (size_t)mt * 128 * 512;
        wsrc = g_wU[1 + 2 * b] + ((size_t)(p * 256) + o * 128) * 512;
        mdst = g_M[b] + ((size_t)p * NTX + mt * 128) * 256 + o * 128;
    } else {
        int zb = bid - 3648;
        int q = zb / 3, mt = zb - q * 3;
        int p = q & 15; q >>= 4;
        int o = q & 1, b = q >> 1;
        vsrc = g_Vz + (size_t)p * VSZ + (size_t)mt * 128 * 512;
        wsrc = g_wU[2 * b] + ((size_t)(p * 256) + o * 128) * 512;
        mdst = g_Mz[b] + ((size_t)p * NTZ + mt * 128) * 256 + o * 128;
    }

    float acc[4][8][4];
#pragma unroll
    for (int t = 0; t < 4; t++)
#pragma unroll
        for (int j = 0; j < 8; j++)
#pragma unroll
            for (int e = 0; e < 4; e++) acc[t][j][e] = 0.f;

    auto copyAB = [&](int g) {
        const int buf = g & 1, c0 = g * 32;
#pragma unroll
        for (int k = 0; k < 8; k++) {
            int id = tid + k * 128;                  // 1024: A
            int row = id >> 3, part = id & 7, comp = part >> 2, kq = part & 3;
            cp16(sBu + buf * ABUF + row * ASTRIDE + comp * 64 + kq * 16,
                 vsrc + (size_t)row * 512 + comp * 256 + c0 + kq * 8);
        }
#pragma unroll
        for (int k = 0; k < 8; k++) {
            int id = tid + k * 128;                  // 1024: B
            int row = id >> 3, part = id & 7, comp = part >> 2, kq = part & 3;
            cp16(sBu + BOFF + buf * ABUF + row * ASTRIDE + comp * 64 + kq * 16,
                 wsrc + (size_t)row * 512 + comp * 256 + c0 + kq * 8);
        }
        cp_commit();
    };

    copyAB(0);
#pragma unroll 1
    for (int g = 0; g < 8; g++) {
        const int buf = g & 1;
        __syncthreads();
        if (g + 1 < 8) { copyAB(g + 1); cp_wait<1>(); }
        else           { cp_wait<0>(); }
        __syncthreads();

        uint32_t aaddr[4], baddr[4];
#pragma unroll
        for (int t = 0; t < 4; t++) {
            int m = warp_m * 64 + t * 16 + (lid & 7) + ((lid >> 3) & 1) * 8;
            aaddr[t] = sBu + buf * ABUF + m * ASTRIDE + ((lid >> 4) << 4);
        }
#pragma unroll
        for (int j = 0; j < 4; j++) {
            int n = warp_n * 64 + j * 16 + (lid & 7) + (lid >> 4) * 8;
            baddr[j] = sBu + BOFF + buf * ABUF + n * ASTRIDE + (((lid >> 3) & 1) << 4);
        }

#pragma unroll
        for (int ks = 0; ks < 2; ks++) {
            uint32_t ah[4][4], al[4][4], bq[4][4];
#pragma unroll
            for (int t = 0; t < 4; t++) LDSM4(ah[t], aaddr[t] + ks * 32);
#pragma unroll
            for (int t = 0; t < 4; t++) LDSM4(al[t], aaddr[t] + ks * 32 + 64);
#pragma unroll
            for (int j = 0; j < 4; j++) LDSM4(bq[j], baddr[j] + ks * 32);
            // hi*hi
#pragma unroll
            for (int t = 0; t < 4; t++)
#pragma unroll
                for (int j = 0; j < 4; j++) {
                    MMA(acc[t][2 * j],     ah[t], bq[j][0], bq[j][1]);
                    MMA(acc[t][2 * j + 1], ah[t], bq[j][2], bq[j][3]);
                }
            // lo*hi
#pragma unroll
            for (int t = 0; t < 4; t++)
#pragma unroll
                for (int j = 0; j < 4; j++) {
                    MMA(acc[t][2 * j],     al[t], bq[j][0], bq[j][1]);
                    MMA(acc[t][2 * j + 1], al[t], bq[j][2], bq[j][3]);
                }
            // hi*lo
#pragma unroll
            for (int j = 0; j < 4; j++) LDSM4(bq[j], baddr[j] + ks * 32 + 64);
#pragma unroll
            for (int t = 0; t < 4; t++)
#pragma unroll
                for (int j = 0; j < 4; j++) {
                    MMA(acc[t][2 * j],     ah[t], bq[j][0], bq[j][1]);
                    MMA(acc[t][2 * j + 1], ah[t], bq[j][2], bq[j][3]);
                }
        }
    }

    // epilogue: direct [tile][oc] fp32 stores (row-major, float2)
#pragma unroll
    for (int t = 0; t < 4; t++) {
        int r = warp_m * 64 + t * 16 + (lid >> 2);
#pragma unroll
        for (int jj = 0; jj < 8; jj++) {
            int c = warp_n * 64 + (jj >> 1) * 16 + (jj & 1) * 8 + (lid & 3) * 2;
            float* base = mdst + (size_t)r * 256 + c;
            *(float2*)base = make_float2(acc[t][jj][0], acc[t][jj][1]);
            *(float2*)(base + 8 * 256) = make_float2(acc[t][jj][2], acc[t][jj][3]);
        }
    }
}

// ============================ inverse transforms =============================
__global__ __launch_bounds__(256)
void inv_x() {
    __shared__ float sOut[64][60];
    __shared__ float sB[64];
    const int ocg = blockIdx.x * 64, img = blockIdx.y, b = blockIdx.z;
    const int tid = threadIdx.x;
    if (tid < 64) sB[tid] = g_bias[1 + 2 * b][ocg + tid];
    __syncthreads();

    const float* Mb = g_M[b];
    for (int ty = 0; ty < 15; ty++) {
#pragma unroll
        for (int k = 0; k < 4; k++) {
            int it = k * 256 + tid;
            if (it < 960) {
                int tx = it >> 6, oc = it & 63;
                size_t gt = (size_t)img * 225 + ty * 15 + tx;
                float Mv[16];
#pragma unroll
                for (int pos = 0; pos < 16; pos++)
                    Mv[pos] = Mb[((size_t)pos * NTX + gt) * 256 + ocg + oc];
                float t0[4], t1[4];
#pragma unroll
                for (int j = 0; j < 4; j++) {
                    t0[j] = Mv[j] + Mv[4 + j] + Mv[8 + j];
                    t1[j] = Mv[4 + j] - Mv[8 + j] - Mv[12 + j];
                }
                float bs = sB[oc];
                sOut[oc][tx * 2]      = t0[0] + t0[1] + t0[2] + bs;
                sOut[oc][tx * 2 + 1]  = t0[1] - t0[2] - t0[3] + bs;
                sOut[oc][30 + tx * 2]     = t1[0] + t1[1] + t1[2] + bs;
                sOut[oc][30 + tx * 2 + 1] = t1[1] - t1[2] - t1[3] + bs;
            }
        }
        __syncthreads();
        float* dst = g_xf[b] + ((size_t)img * 256 + ocg) * 900 + (2 * ty) * 30;
#pragma unroll
        for (int k = 0; k < 15; k++) {
            int f = k * 256 + tid;                  // 3840 floats
            int oc = f / 60, rem = f - oc * 60;
            dst[(size_t)oc * 900 + rem] = sOut[oc][rem];
        }
        __syncthreads();
    }
}

__global__ __launch_bounds__(256)
void inv_z() {
    __shared__ float sOut[256 * 36];
    const int img = blockIdx.x, b = blockIdx.y;
    const int oc = threadIdx.x;
    const float bs = g_bias[2 * b][oc];
    const float* Mb = g_Mz[b];
#pragma unroll
    for (int t = 0; t < 9; t++) {
        int ty = t / 3, tx = t - ty * 3;
        float Mv[16];
#pragma unroll
        for (int pos = 0; pos < 16; pos++)
            Mv[pos] = Mb[((size_t)pos * NTZ + img * 9 + t) * 256 + oc];
        float t0[4], t1[4];
#pragma unroll
        for (int j = 0; j < 4; j++) {
            t0[j] = Mv[j] + Mv[4 + j] + Mv[8 + j];
            t1[j] = Mv[4 + j] - Mv[8 + j] - Mv[12 + j];
        }
        sOut[oc * 36 + (2 * ty) * 6 + 2 * tx]         = t0[0] + t0[1] + t0[2] + bs;
        sOut[oc * 36 + (2 * ty) * 6 + 2 * tx + 1]     = t0[1] - t0[2] - t0[3] + bs;
        sOut[oc * 36 + (2 * ty + 1) * 6 + 2 * tx]     = t1[0] + t1[1] + t1[2] + bs;
        sOut[oc * 36 + (2 * ty + 1) * 6 + 2 * tx + 1] = t1[1] - t1[2] - t1[3] + bs;
    }
    __syncthreads();
    float* dst = g_zf[b] + (size_t)img * 256 * 36;
#pragma unroll
    for (int k = 0; k < 36; k++) {
        int f = k * 256 + threadIdx.x;              // 9216 floats
        dst[f] = sOut[f];
    }
}

// ============================ depthwise xcorr ================================
__global__ __launch_bounds__(640)
void xcorr_kernel(float* __restrict__ out) {
    __shared__ float s_x[900];
    __shared__ float s_z[36];
    const int branch = blockIdx.y;
    const int bc = blockIdx.x;
    const int tid = threadIdx.x;
    if (tid < 36) s_z[tid] = g_zf[branch][(size_t)bc * 36 + tid];
    for (int i = tid; i < 900; i += 640) s_x[i] = g_xf[branch][(size_t)bc * 900 + i];
    __syncthreads();
    if (tid < 625) {
        int oy = tid / 25, ox = tid % 25;
        float s = 0.f;
#pragma unroll
        for (int u = 0; u < 6; u++)
#pragma unroll
            for (int v = 0; v < 6; v++)
                s = fmaf(s_z[u * 6 + v], s_x[(oy + u) * 30 + ox + v], s);
        out[(size_t)branch * OSZ + (size_t)bc * 625 + tid] = s;
    }
}

// ============================ launch =========================================
extern "C" void kernel_launch(void* const* d_in, const int* in_sizes, int n_in,
                              void* d_out, int out_size) {
    const float* z = (const float*)d_in[0];
    const float* x = (const float*)d_in[1];

    PrepArgs pa;
    for (int p = 0; p < 4; p++) {
        pa.w[p] = (const float*)d_in[2 + p * 5 + 0];
        pa.g[p] = (const float*)d_in[2 + p * 5 + 1];
        pa.b[p] = (const float*)d_in[2 + p * 5 + 2];
        pa.m[p] = (const float*)d_in[2 + p * 5 + 3];
        pa.v[p] = (const float*)d_in[2 + p * 5 + 4];
    }

    cudaFuncSetAttribute(wino_gemm,
                         cudaFuncAttributeMaxDynamicSharedMemorySize, GEMM_SMEM);
    cudaFuncSetAttribute(wino_gemm,
                         cudaFuncAttributePreferredSharedMemoryCarveout, 100);

    prep_kernel<<<1024, 256>>>(pa);
    xform_x<<<dim3(32, 32), 256>>>(x);
    xform_z<<<dim3(32, 32), 128>>>(z);
    wino_gemm<<<3840, 128, GEMM_SMEM>>>();
    inv_x<<<dim3(4, 32, 2), 256>>>();
    inv_z<<<dim3(32, 2), 256>>>();
    xcorr_kernel<<<dim3(NB * COUT, 2), 640>>>((float*)d_out);
}